// round 1
// baseline (speedup 1.0000x reference)
#include <cuda_runtime.h>
#include <math.h>

#define N_NODES 4096
#define NFEAT   1024
#define NHID    128
#define NHEADS  8
#define NCLASS  64
#define ALPHA   0.2f
#define NEG_INF -9e15f

// ---------------- scratch (static device memory; no allocation) ----------------
__device__ float g_Wh  [NHEADS * N_NODES * NHID];   // 16 MB
__device__ float g_f1  [NHEADS * N_NODES];
__device__ float g_f2  [NHEADS * N_NODES];
__device__ float g_m   [NHEADS * N_NODES];
__device__ float g_Z   [NHEADS * N_NODES];
__device__ float g_hcat[N_NODES * NHEADS * NHID];   // 16 MB
__device__ float g_Who [N_NODES * NCLASS];
__device__ float g_g1  [N_NODES];
__device__ float g_g2  [N_NODES];
__device__ float g_mo  [N_NODES];
__device__ float g_Zo  [N_NODES];
__device__ float g_obuf[N_NODES * NCLASS];

__device__ __forceinline__ float lrelu(float x) { return x > 0.f ? x : ALPHA * x; }

// ---------------- generic fp32 tiled GEMM: C = A[M,K] @ B[K,Nc] ----------------
// blockIdx.z selects a "head": B += z*strideB, C += z*strideC.
template<int BM, int BN, int BK, int TM, int TN>
__global__ void sgemm_kernel(const float* __restrict__ A, const float* __restrict__ B,
                             float* __restrict__ C, int M, int Nc, int K,
                             long strideB, long strideC)
{
    __shared__ float As[BK][BM + 4];
    __shared__ float Bs[BK][BN];

    B += (long)blockIdx.z * strideB;
    C += (long)blockIdx.z * strideC;

    const int tid = threadIdx.x;                 // 256 threads
    const int tx  = tid % (BN / TN);
    const int ty  = tid / (BN / TN);
    const int row0 = blockIdx.y * BM;

    float acc[TM][TN];
#pragma unroll
    for (int i = 0; i < TM; i++)
#pragma unroll
        for (int j = 0; j < TN; j++) acc[i][j] = 0.f;

    for (int k0 = 0; k0 < K; k0 += BK) {
        // A tile (BM x BK), stored transposed into As[k][m]
        for (int idx = tid; idx < BM * (BK / 4); idx += 256) {
            int r  = idx / (BK / 4);
            int kq = idx % (BK / 4);
            float4 v = *(const float4*)&A[(long)(row0 + r) * K + k0 + kq * 4];
            As[kq * 4 + 0][r] = v.x;
            As[kq * 4 + 1][r] = v.y;
            As[kq * 4 + 2][r] = v.z;
            As[kq * 4 + 3][r] = v.w;
        }
        // B tile (BK x BN)
        for (int idx = tid; idx < BK * (BN / 4); idx += 256) {
            int r = idx / (BN / 4);
            int c = idx % (BN / 4);
            float4 v = *(const float4*)&B[(long)(k0 + r) * Nc + c * 4];
            *(float4*)&Bs[r][c * 4] = v;
        }
        __syncthreads();

#pragma unroll
        for (int kk = 0; kk < BK; kk++) {
            float a[TM], b[TN];
#pragma unroll
            for (int i = 0; i < TM; i++) a[i] = As[kk][ty * TM + i];
#pragma unroll
            for (int j = 0; j < TN; j++) b[j] = Bs[kk][tx * TN + j];
#pragma unroll
            for (int i = 0; i < TM; i++)
#pragma unroll
                for (int j = 0; j < TN; j++) acc[i][j] = fmaf(a[i], b[j], acc[i][j]);
        }
        __syncthreads();
    }

#pragma unroll
    for (int i = 0; i < TM; i++) {
        int r = row0 + ty * TM + i;
#pragma unroll
        for (int j = 0; j < TN; j++)
            C[(long)r * Nc + tx * TN + j] = acc[i][j];
    }
}

// ---------------- f1/f2 (or g1/g2): per-row dot with two vectors ----------------
__global__ void dots_kernel(const float* __restrict__ Mtx, const float* __restrict__ v1,
                            const float* __restrict__ v2, float* __restrict__ o1,
                            float* __restrict__ o2, int D, int rowsPerHead, int totalRows)
{
    int warp = (blockIdx.x * blockDim.x + threadIdx.x) >> 5;
    int lane = threadIdx.x & 31;
    if (warp >= totalRows) return;
    int h = warp / rowsPerHead;
    const float* row = Mtx + (long)warp * D;
    float s1 = 0.f, s2 = 0.f;
    for (int d = lane; d < D; d += 32) {
        float x = row[d];
        s1 += x * v1[h * D + d];
        s2 += x * v2[h * D + d];
    }
#pragma unroll
    for (int o = 16; o > 0; o >>= 1) {
        s1 += __shfl_down_sync(0xffffffffu, s1, o);
        s2 += __shfl_down_sync(0xffffffffu, s2, o);
    }
    if (lane == 0) { o1[warp] = s1; o2[warp] = s2; }
}

// ---------------- per-row softmax stats: m = max_j e, Z = sum_j exp(e - m) ------
// e = mask ? lrelu(f1[i]+f2[j]) : NEG_INF  (NEG_INF entries included, matching ref)
__global__ void stats_kernel(const int* __restrict__ adj, const float* __restrict__ f1,
                             const float* __restrict__ f2, float* __restrict__ mout,
                             float* __restrict__ Zout, int H)
{
    const int i   = blockIdx.x;
    const int tid = threadIdx.x;
    __shared__ float red[256];
    const int* arow = adj + (long)i * N_NODES;

    for (int h = 0; h < H; h++) {
        const float f1i = f1[h * N_NODES + i];
        const float* f2h = f2 + h * N_NODES;

        // pass 1: max
        float mt = -INFINITY;
        for (int j = tid; j < N_NODES; j += 256) {
            float e = arow[j] ? lrelu(f1i + f2h[j]) : NEG_INF;
            mt = fmaxf(mt, e);
        }
        red[tid] = mt; __syncthreads();
        for (int s = 128; s > 0; s >>= 1) {
            if (tid < s) red[tid] = fmaxf(red[tid], red[tid + s]);
            __syncthreads();
        }
        float mv = red[0];
        __syncthreads();

        // pass 2: sum of exp(e - m)
        float st = 0.f;
        for (int j = tid; j < N_NODES; j += 256) {
            float e = arow[j] ? lrelu(f1i + f2h[j]) : NEG_INF;
            st += __expf(e - mv);
        }
        red[tid] = st; __syncthreads();
        for (int s = 128; s > 0; s >>= 1) {
            if (tid < s) red[tid] += red[tid + s];
            __syncthreads();
        }
        if (tid == 0) { mout[h * N_NODES + i] = mv; Zout[h * N_NODES + i] = red[0]; }
        __syncthreads();
    }
}

// ---------------- attention apply: out = softmax(e) @ Whv, fused, + ELU --------
// Builds P tiles (exp(e - m)) on the fly in shared, register-tiled fp32 MMA.
template<int BM, int BN, int TM, int TN>
__global__ void gat_agg_kernel(const int* __restrict__ adj,
                               const float* __restrict__ Whv,   // [H][N][BN]
                               const float* __restrict__ f1,
                               const float* __restrict__ f2,
                               const float* __restrict__ mrow,
                               const float* __restrict__ Zrow,
                               float* __restrict__ out, int outStride, int outColScale)
{
    constexpr int BK = 32;
    __shared__ float Ps [BK][BM + 1];
    __shared__ float Whs[BK][BN];
    __shared__ float sf1[BM];
    __shared__ float sm [BM];
    __shared__ float sZ [BM];

    const int tid = threadIdx.x;                 // 256 threads
    const int tx  = tid % (BN / TN);
    const int ty  = tid / (BN / TN);
    const int h   = blockIdx.z;
    const int i0  = blockIdx.y * BM;
    const int hN  = h * N_NODES;
    const long whBase = (long)h * N_NODES * BN;
    const int colOff  = h * outColScale;

    for (int i = tid; i < BM; i += 256) {
        sf1[i] = f1[hN + i0 + i];
        sm [i] = mrow[hN + i0 + i];
        sZ [i] = Zrow[hN + i0 + i];
    }
    __syncthreads();

    float acc[TM][TN];
#pragma unroll
    for (int i = 0; i < TM; i++)
#pragma unroll
        for (int j = 0; j < TN; j++) acc[i][j] = 0.f;

    for (int j0 = 0; j0 < N_NODES; j0 += BK) {
        // build P tile: Ps[j][i] = exp(e(i, j0+j) - m_i)
        for (int idx = tid; idx < BM * BK; idx += 256) {
            int i  = idx / BK;
            int j  = idx % BK;
            int jj = j0 + j;
            int a  = adj[(long)(i0 + i) * N_NODES + jj];
            float e = a ? lrelu(sf1[i] + f2[hN + jj]) : NEG_INF;
            Ps[j][i] = __expf(e - sm[i]);
        }
        // Wh tile
        for (int idx = tid; idx < BK * (BN / 4); idx += 256) {
            int r = idx / (BN / 4);
            int c = idx % (BN / 4);
            float4 v = *(const float4*)&Whv[whBase + (long)(j0 + r) * BN + c * 4];
            *(float4*)&Whs[r][c * 4] = v;
        }
        __syncthreads();

#pragma unroll
        for (int kk = 0; kk < BK; kk++) {
            float a[TM], b[TN];
#pragma unroll
            for (int i = 0; i < TM; i++) a[i] = Ps[kk][ty * TM + i];
#pragma unroll
            for (int j = 0; j < TN; j++) b[j] = Whs[kk][tx * TN + j];
#pragma unroll
            for (int i = 0; i < TM; i++)
#pragma unroll
                for (int j = 0; j < TN; j++) acc[i][j] = fmaf(a[i], b[j], acc[i][j]);
        }
        __syncthreads();
    }

    // epilogue: normalize by Z, ELU, scatter to concatenated layout
#pragma unroll
    for (int i = 0; i < TM; i++) {
        int r = ty * TM + i;
        float invZ = 1.f / sZ[r];
#pragma unroll
        for (int j = 0; j < TN; j++) {
            float v = acc[i][j] * invZ;
            v = v > 0.f ? v : expm1f(v);
            out[(long)(i0 + r) * outStride + colOff + tx * TN + j] = v;
        }
    }
}

// ---------------- final log_softmax over 64 classes, warp per row --------------
__global__ void lsm_kernel(const float* __restrict__ in, float* __restrict__ out)
{
    int warp = (blockIdx.x * blockDim.x + threadIdx.x) >> 5;
    int lane = threadIdx.x & 31;
    if (warp >= N_NODES) return;
    const float* row = in + (long)warp * NCLASS;
    float v0 = row[lane];
    float v1 = row[lane + 32];
    float m = fmaxf(v0, v1);
#pragma unroll
    for (int o = 16; o > 0; o >>= 1) m = fmaxf(m, __shfl_xor_sync(0xffffffffu, m, o));
    float s = expf(v0 - m) + expf(v1 - m);
#pragma unroll
    for (int o = 16; o > 0; o >>= 1) s += __shfl_xor_sync(0xffffffffu, s, o);
    float ls = m + logf(s);
    out[(long)warp * NCLASS + lane]      = v0 - ls;
    out[(long)warp * NCLASS + lane + 32] = v1 - ls;
}

// ---------------- launch ----------------
extern "C" void kernel_launch(void* const* d_in, const int* in_sizes, int n_in,
                              void* d_out, int out_size)
{
    const float* x   = (const float*)d_in[0];
    const int*   adj = (const int*)  d_in[1];
    const float* W   = (const float*)d_in[2];
    const float* a1  = (const float*)d_in[3];
    const float* a2  = (const float*)d_in[4];
    const float* Wo  = (const float*)d_in[5];
    const float* ao1 = (const float*)d_in[6];
    const float* ao2 = (const float*)d_in[7];
    float* out = (float*)d_out;

    float *Wh, *f1, *f2, *m, *Z, *hcat, *Who, *g1d, *g2d, *mo, *Zo, *obuf;
    cudaGetSymbolAddress((void**)&Wh,   g_Wh);
    cudaGetSymbolAddress((void**)&f1,   g_f1);
    cudaGetSymbolAddress((void**)&f2,   g_f2);
    cudaGetSymbolAddress((void**)&m,    g_m);
    cudaGetSymbolAddress((void**)&Z,    g_Z);
    cudaGetSymbolAddress((void**)&hcat, g_hcat);
    cudaGetSymbolAddress((void**)&Who,  g_Who);
    cudaGetSymbolAddress((void**)&g1d,  g_g1);
    cudaGetSymbolAddress((void**)&g2d,  g_g2);
    cudaGetSymbolAddress((void**)&mo,   g_mo);
    cudaGetSymbolAddress((void**)&Zo,   g_Zo);
    cudaGetSymbolAddress((void**)&obuf, g_obuf);

    // 1) Wh[h] = x @ W[h]   ([4096,1024]@[1024,128] x 8)
    {
        dim3 grid(1, N_NODES / 128, NHEADS);
        sgemm_kernel<128, 128, 16, 8, 8><<<grid, 256>>>(
            x, W, Wh, N_NODES, NHID, NFEAT,
            (long)NFEAT * NHID, (long)N_NODES * NHID);
    }
    // 2) f1, f2
    dots_kernel<<<(NHEADS * N_NODES) / 8, 256>>>(Wh, a1, a2, f1, f2, NHID, N_NODES, NHEADS * N_NODES);
    // 3) softmax stats layer 1
    stats_kernel<<<N_NODES, 256>>>(adj, f1, f2, m, Z, NHEADS);
    // 4) attention apply layer 1 (+ELU, concat layout)
    {
        dim3 grid(1, N_NODES / 128, NHEADS);
        gat_agg_kernel<128, 128, 8, 8><<<grid, 256>>>(
            adj, Wh, f1, f2, m, Z, hcat, NHEADS * NHID, NHID);
    }
    // 5) Who = hcat @ Wo   ([4096,1024]@[1024,64])
    {
        dim3 grid(1, N_NODES / 64, 1);
        sgemm_kernel<64, 64, 16, 4, 4><<<grid, 256>>>(
            hcat, Wo, Who, N_NODES, NCLASS, NHEADS * NHID, 0, 0);
    }
    // 6) g1, g2
    dots_kernel<<<N_NODES / 8, 256>>>(Who, ao1, ao2, g1d, g2d, NCLASS, N_NODES, N_NODES);
    // 7) softmax stats output layer
    stats_kernel<<<N_NODES, 256>>>(adj, g1d, g2d, mo, Zo, 1);
    // 8) attention apply output layer (+ELU)
    {
        dim3 grid(1, N_NODES / 32, 1);
        gat_agg_kernel<32, 64, 2, 4><<<grid, 256>>>(
            adj, Who, g1d, g2d, mo, Zo, obuf, NCLASS, 0);
    }
    // 9) log_softmax -> d_out
    lsm_kernel<<<N_NODES / 8, 256>>>(obuf, out);
}

// round 5
// speedup vs baseline: 1.2171x; 1.2171x over previous
#include <cuda_runtime.h>
#include <cuda_bf16.h>
#include <math.h>
#include <stdint.h>

#define N_NODES 4096
#define NFEAT   1024
#define NHID    128
#define NHEADS  8
#define NCLASS  64
#define ALPHA   0.2f
#define NEG_INF -9e15f
#define NCHUNK  (N_NODES / 16)   // 256 k-chunks of 16
#define NTILE   (NHID / 8)       // 16 n-tiles of 8

// ---------------- scratch (static device memory; no allocation) ----------------
__device__ float g_Wh  [NHEADS * N_NODES * NHID];   // 16 MB
__device__ float g_f1  [NHEADS * N_NODES];
__device__ float g_f2  [NHEADS * N_NODES];
__device__ float g_m   [NHEADS * N_NODES];
__device__ float g_hcat[N_NODES * NHEADS * NHID];   // 16 MB
__device__ float g_Who [N_NODES * NCLASS];
__device__ float g_g1  [N_NODES];
__device__ float g_g2  [N_NODES];
__device__ float g_mo  [N_NODES];
__device__ float g_Zo  [N_NODES];
__device__ float g_obuf[N_NODES * NCLASS];
// Wh pre-packed into mma.sync B-fragment layout:
// [h][chunk][tile][lane] = uint4 {b0b1_hi, b2b3_hi, b0b1_lo, b2b3_lo}
__device__ uint4 g_bfrag[NHEADS * NCHUNK * NTILE * 32];   // 16 MB

__device__ __forceinline__ float lrelu(float x) { return fmaxf(x, ALPHA * x); }
__device__ __forceinline__ float elu_f(float x) { return x > 0.f ? x : expm1f(x); }

__device__ __forceinline__ uint32_t pack_bf2(float lo, float hi) {
    __nv_bfloat162 v;
    v.x = __float2bfloat16(lo);
    v.y = __float2bfloat16(hi);
    return *(uint32_t*)&v;
}

// ---------------- generic fp32 tiled GEMM ----------------
template<int BM, int BN, int BK, int TM, int TN>
__global__ void sgemm_kernel(const float* __restrict__ A, const float* __restrict__ B,
                             float* __restrict__ C, int M, int Nc, int K,
                             long strideB, long strideC)
{
    __shared__ float As[BK][BM + 4];
    __shared__ float Bs[BK][BN];
    B += (long)blockIdx.z * strideB;
    C += (long)blockIdx.z * strideC;
    const int tid = threadIdx.x;
    const int tx  = tid % (BN / TN);
    const int ty  = tid / (BN / TN);
    const int row0 = blockIdx.y * BM;
    float acc[TM][TN];
#pragma unroll
    for (int i = 0; i < TM; i++)
#pragma unroll
        for (int j = 0; j < TN; j++) acc[i][j] = 0.f;
    for (int k0 = 0; k0 < K; k0 += BK) {
        for (int idx = tid; idx < BM * (BK / 4); idx += 256) {
            int r  = idx / (BK / 4);
            int kq = idx % (BK / 4);
            float4 v = *(const float4*)&A[(long)(row0 + r) * K + k0 + kq * 4];
            As[kq * 4 + 0][r] = v.x; As[kq * 4 + 1][r] = v.y;
            As[kq * 4 + 2][r] = v.z; As[kq * 4 + 3][r] = v.w;
        }
        for (int idx = tid; idx < BK * (BN / 4); idx += 256) {
            int r = idx / (BN / 4);
            int c = idx % (BN / 4);
            float4 v = *(const float4*)&B[(long)(k0 + r) * Nc + c * 4];
            *(float4*)&Bs[r][c * 4] = v;
        }
        __syncthreads();
#pragma unroll
        for (int kk = 0; kk < BK; kk++) {
            float a[TM], b[TN];
#pragma unroll
            for (int i = 0; i < TM; i++) a[i] = As[kk][ty * TM + i];
#pragma unroll
            for (int j = 0; j < TN; j++) b[j] = Bs[kk][tx * TN + j];
#pragma unroll
            for (int i = 0; i < TM; i++)
#pragma unroll
                for (int j = 0; j < TN; j++) acc[i][j] = fmaf(a[i], b[j], acc[i][j]);
        }
        __syncthreads();
    }
#pragma unroll
    for (int i = 0; i < TM; i++) {
        int r = row0 + ty * TM + i;
#pragma unroll
        for (int j = 0; j < TN; j++)
            C[(long)r * Nc + tx * TN + j] = acc[i][j];
    }
}

// ---------------- per-row dot with two vectors ----------------
__global__ void dots_kernel(const float* __restrict__ Mtx, const float* __restrict__ v1,
                            const float* __restrict__ v2, float* __restrict__ o1,
                            float* __restrict__ o2, int D, int rowsPerHead, int totalRows)
{
    int warp = (blockIdx.x * blockDim.x + threadIdx.x) >> 5;
    int lane = threadIdx.x & 31;
    if (warp >= totalRows) return;
    int h = warp / rowsPerHead;
    const float* row = Mtx + (long)warp * D;
    float s1 = 0.f, s2 = 0.f;
    for (int d = lane; d < D; d += 32) {
        float x = row[d];
        s1 += x * v1[h * D + d];
        s2 += x * v2[h * D + d];
    }
#pragma unroll
    for (int o = 16; o > 0; o >>= 1) {
        s1 += __shfl_down_sync(0xffffffffu, s1, o);
        s2 += __shfl_down_sync(0xffffffffu, s2, o);
    }
    if (lane == 0) { o1[warp] = s1; o2[warp] = s2; }
}

// ---------------- layer-1 softmax max via monotone lrelu ----------------
// m[h][i] = (no neighbors) ? NEG_INF : lrelu(f1[h][i] + max_{j:adj} f2[h][j])
__global__ void maxstat_kernel(const int* __restrict__ adj, const float* __restrict__ f1,
                               const float* __restrict__ f2, float* __restrict__ mout)
{
    __shared__ float sred[8 * 8];
    const int i = blockIdx.x, tid = threadIdx.x, wid = tid >> 5, lane = tid & 31;
    float mx[8];
#pragma unroll
    for (int h = 0; h < 8; h++) mx[h] = -INFINITY;
    const int4* arow = (const int4*)(adj + (size_t)i * N_NODES);
    for (int q = tid; q < N_NODES / 4; q += 256) {
        int4 a = arow[q];
        int j = q * 4;
#pragma unroll
        for (int h = 0; h < 8; h++) {
            float4 fv = *(const float4*)(f2 + h * N_NODES + j);
            if (a.x) mx[h] = fmaxf(mx[h], fv.x);
            if (a.y) mx[h] = fmaxf(mx[h], fv.y);
            if (a.z) mx[h] = fmaxf(mx[h], fv.z);
            if (a.w) mx[h] = fmaxf(mx[h], fv.w);
        }
    }
#pragma unroll
    for (int h = 0; h < 8; h++)
#pragma unroll
        for (int o = 16; o > 0; o >>= 1) mx[h] = fmaxf(mx[h], __shfl_xor_sync(0xffffffffu, mx[h], o));
    if (lane == 0)
#pragma unroll
        for (int h = 0; h < 8; h++) sred[h * 8 + wid] = mx[h];
    __syncthreads();
    if (tid < 8) {
        float m2 = sred[tid * 8];
#pragma unroll
        for (int w = 1; w < 8; w++) m2 = fmaxf(m2, sred[tid * 8 + w]);
        mout[tid * N_NODES + i] = (m2 == -INFINITY) ? NEG_INF
                                                    : lrelu(f1[tid * N_NODES + i] + m2);
    }
}

// ---------------- prep: Wh -> split-bf16 mma.sync B fragments ----------------
// B tile for chunk c (k rows j0..j0+15), tile t (cols d0..d0+7), lane l:
//   tg = l&3, g = l>>2
//   b0 = Wh[j0+tg*2][d0+g], b1 = Wh[j0+tg*2+1][d0+g],
//   b2 = Wh[j0+tg*2+8][d0+g], b3 = Wh[j0+tg*2+9][d0+g]
__global__ void prep_bfrag_kernel(const float* __restrict__ Wh, uint4* __restrict__ bf)
{
    const int c = blockIdx.x, h = blockIdx.y, tid = threadIdx.x;   // 512 threads
    const int t  = tid >> 5, l = tid & 31;
    const int tg = l & 3,  g = l >> 2;
    const float* src = Wh + (size_t)h * N_NODES * NHID + (size_t)(c * 16 + tg * 2) * NHID + t * 8 + g;
    float b0 = src[0];
    float b1 = src[NHID];
    float b2 = src[8 * NHID];
    float b3 = src[9 * NHID];
    float h0 = __bfloat162float(__float2bfloat16(b0));
    float h1 = __bfloat162float(__float2bfloat16(b1));
    float h2 = __bfloat162float(__float2bfloat16(b2));
    float h3 = __bfloat162float(__float2bfloat16(b3));
    uint4 v;
    v.x = pack_bf2(b0, b1);                 // hi pair (reg0)
    v.y = pack_bf2(b2, b3);                 // hi pair (reg1)
    v.z = pack_bf2(b0 - h0, b1 - h1);       // lo pair (reg0)
    v.w = pack_bf2(b2 - h2, b3 - h3);       // lo pair (reg1)
    bf[(((size_t)h * NCHUNK + c) * NTILE + t) * 32 + l] = v;
}

// ---------------- mma.sync split-bf16 attention apply (layer 1) ----------------
// grid (32, 8): 128 rows per CTA, 8 warps, warp w -> rows i0+w*16+{g, g+8}.
// A fragments (P = exp(e - m)) built directly in registers; B from g_bfrag;
// Z accumulated in-register; epilogue /Z + ELU into concat layout.
__global__ void __launch_bounds__(256)
agg_mma_kernel(const int* __restrict__ adj, const float* __restrict__ f1,
               const float* __restrict__ f2, const float* __restrict__ mrow,
               const uint4* __restrict__ bfrag, float* __restrict__ out)
{
    const int tid  = threadIdx.x;
    const int w    = tid >> 5;
    const int lane = tid & 31;
    const int tg   = lane & 3;
    const int g    = lane >> 2;
    const int h    = blockIdx.y;
    const int i0   = blockIdx.x * 128;
    const int hN   = h * N_NODES;

    const int r0 = i0 + w * 16 + g;       // global row for a0/a2, c0/c1
    const int r1 = r0 + 8;                // global row for a1/a3, c2/c3

    const float f1a = f1[hN + r0], ma = mrow[hN + r0];
    const float f1b = f1[hN + r1], mb = mrow[hN + r1];
    const int* adjA = adj + (size_t)r0 * N_NODES;
    const int* adjB = adj + (size_t)r1 * N_NODES;
    const float* f2h = f2 + hN;
    const uint4* bfh = bfrag + (size_t)h * NCHUNK * NTILE * 32 + lane;

    float acc[NTILE][4];
#pragma unroll
    for (int t = 0; t < NTILE; t++)
#pragma unroll
        for (int q = 0; q < 4; q++) acc[t][q] = 0.f;

    float z0 = 0.f, z1 = 0.f;

    for (int c = 0; c < NCHUNK; c++) {
        const int jA = c * 16 + tg * 2;   // cols jA, jA+1
        const int jB = jA + 8;            // cols jB, jB+1

        int2 aA0 = *(const int2*)(adjA + jA);
        int2 aA1 = *(const int2*)(adjA + jB);
        int2 aB0 = *(const int2*)(adjB + jA);
        int2 aB1 = *(const int2*)(adjB + jB);
        float2 fA = *(const float2*)(f2h + jA);
        float2 fB = *(const float2*)(f2h + jB);

        float p00 = __expf((aA0.x ? lrelu(f1a + fA.x) : NEG_INF) - ma);
        float p01 = __expf((aA0.y ? lrelu(f1a + fA.y) : NEG_INF) - ma);
        float p02 = __expf((aA1.x ? lrelu(f1a + fB.x) : NEG_INF) - ma);
        float p03 = __expf((aA1.y ? lrelu(f1a + fB.y) : NEG_INF) - ma);
        float p10 = __expf((aB0.x ? lrelu(f1b + fA.x) : NEG_INF) - mb);
        float p11 = __expf((aB0.y ? lrelu(f1b + fA.y) : NEG_INF) - mb);
        float p12 = __expf((aB1.x ? lrelu(f1b + fB.x) : NEG_INF) - mb);
        float p13 = __expf((aB1.y ? lrelu(f1b + fB.y) : NEG_INF) - mb);

        z0 += (p00 + p01) + (p02 + p03);
        z1 += (p10 + p11) + (p12 + p13);

        // hi / lo A fragments
        uint32_t a0h = pack_bf2(p00, p01);
        uint32_t a1h = pack_bf2(p10, p11);
        uint32_t a2h = pack_bf2(p02, p03);
        uint32_t a3h = pack_bf2(p12, p13);
        float q00 = p00 - __bfloat162float(__float2bfloat16(p00));
        float q01 = p01 - __bfloat162float(__float2bfloat16(p01));
        float q02 = p02 - __bfloat162float(__float2bfloat16(p02));
        float q03 = p03 - __bfloat162float(__float2bfloat16(p03));
        float q10 = p10 - __bfloat162float(__float2bfloat16(p10));
        float q11 = p11 - __bfloat162float(__float2bfloat16(p11));
        float q12 = p12 - __bfloat162float(__float2bfloat16(p12));
        float q13 = p13 - __bfloat162float(__float2bfloat16(p13));
        uint32_t a0l = pack_bf2(q00, q01);
        uint32_t a1l = pack_bf2(q10, q11);
        uint32_t a2l = pack_bf2(q02, q03);
        uint32_t a3l = pack_bf2(q12, q13);

        const uint4* bp = bfh + (size_t)c * NTILE * 32;
#pragma unroll
        for (int t = 0; t < NTILE; t++) {
            uint4 b = bp[t * 32];
            asm volatile("mma.sync.aligned.m16n8k16.row.col.f32.bf16.bf16.f32 "
                         "{%0,%1,%2,%3}, {%4,%5,%6,%7}, {%8,%9}, {%0,%1,%2,%3};"
                         : "+f"(acc[t][0]), "+f"(acc[t][1]), "+f"(acc[t][2]), "+f"(acc[t][3])
                         : "r"(a0h), "r"(a1h), "r"(a2h), "r"(a3h), "r"(b.x), "r"(b.y));
            asm volatile("mma.sync.aligned.m16n8k16.row.col.f32.bf16.bf16.f32 "
                         "{%0,%1,%2,%3}, {%4,%5,%6,%7}, {%8,%9}, {%0,%1,%2,%3};"
                         : "+f"(acc[t][0]), "+f"(acc[t][1]), "+f"(acc[t][2]), "+f"(acc[t][3])
                         : "r"(a0h), "r"(a1h), "r"(a2h), "r"(a3h), "r"(b.z), "r"(b.w));
            asm volatile("mma.sync.aligned.m16n8k16.row.col.f32.bf16.bf16.f32 "
                         "{%0,%1,%2,%3}, {%4,%5,%6,%7}, {%8,%9}, {%0,%1,%2,%3};"
                         : "+f"(acc[t][0]), "+f"(acc[t][1]), "+f"(acc[t][2]), "+f"(acc[t][3])
                         : "r"(a0l), "r"(a1l), "r"(a2l), "r"(a3l), "r"(b.x), "r"(b.y));
        }
    }

    // Z reduce across the 4 lanes of each row group (lane%4)
    z0 += __shfl_xor_sync(0xffffffffu, z0, 1);
    z0 += __shfl_xor_sync(0xffffffffu, z0, 2);
    z1 += __shfl_xor_sync(0xffffffffu, z1, 1);
    z1 += __shfl_xor_sync(0xffffffffu, z1, 2);
    const float iz0 = 1.f / z0;
    const float iz1 = 1.f / z1;

    float* row0 = out + (size_t)r0 * (NHEADS * NHID) + h * NHID + tg * 2;
    float* row1 = out + (size_t)r1 * (NHEADS * NHID) + h * NHID + tg * 2;
#pragma unroll
    for (int t = 0; t < NTILE; t++) {
        float2 v0, v1;
        v0.x = elu_f(acc[t][0] * iz0);
        v0.y = elu_f(acc[t][1] * iz0);
        v1.x = elu_f(acc[t][2] * iz1);
        v1.y = elu_f(acc[t][3] * iz1);
        *(float2*)(row0 + t * 8) = v0;
        *(float2*)(row1 + t * 8) = v1;
    }
}

// ---------------- layer-2 softmax stats (H=1) ----------------
__global__ void stats_kernel(const int* __restrict__ adj, const float* __restrict__ f1,
                             const float* __restrict__ f2, float* __restrict__ mout,
                             float* __restrict__ Zout, int H)
{
    const int i   = blockIdx.x;
    const int tid = threadIdx.x;
    __shared__ float red[256];
    const int* arow = adj + (long)i * N_NODES;
    for (int h = 0; h < H; h++) {
        const float f1i = f1[h * N_NODES + i];
        const float* f2h = f2 + h * N_NODES;
        float mt = -INFINITY;
        for (int j = tid; j < N_NODES; j += 256) {
            float e = arow[j] ? lrelu(f1i + f2h[j]) : NEG_INF;
            mt = fmaxf(mt, e);
        }
        red[tid] = mt; __syncthreads();
        for (int s = 128; s > 0; s >>= 1) {
            if (tid < s) red[tid] = fmaxf(red[tid], red[tid + s]);
            __syncthreads();
        }
        float mv = red[0];
        __syncthreads();
        float st = 0.f;
        for (int j = tid; j < N_NODES; j += 256) {
            float e = arow[j] ? lrelu(f1i + f2h[j]) : NEG_INF;
            st += __expf(e - mv);
        }
        red[tid] = st; __syncthreads();
        for (int s = 128; s > 0; s >>= 1) {
            if (tid < s) red[tid] += red[tid + s];
            __syncthreads();
        }
        if (tid == 0) { mout[h * N_NODES + i] = mv; Zout[h * N_NODES + i] = red[0]; }
        __syncthreads();
    }
}

// ---------------- layer-2 fp32 attention apply ----------------
template<int BM, int BN, int TM, int TN>
__global__ void gat_agg_kernel(const int* __restrict__ adj,
                               const float* __restrict__ Whv,
                               const float* __restrict__ f1,
                               const float* __restrict__ f2,
                               const float* __restrict__ mrow,
                               const float* __restrict__ Zrow,
                               float* __restrict__ out, int outStride, int outColScale)
{
    constexpr int BK = 32;
    __shared__ float Ps [BK][BM + 1];
    __shared__ float Whs[BK][BN];
    __shared__ float sf1[BM];
    __shared__ float sm [BM];
    __shared__ float sZ [BM];
    const int tid = threadIdx.x;
    const int tx  = tid % (BN / TN);
    const int ty  = tid / (BN / TN);
    const int h   = blockIdx.z;
    const int i0  = blockIdx.y * BM;
    const int hN  = h * N_NODES;
    const long whBase = (long)h * N_NODES * BN;
    const int colOff  = h * outColScale;
    for (int i = tid; i < BM; i += 256) {
        sf1[i] = f1[hN + i0 + i];
        sm [i] = mrow[hN + i0 + i];
        sZ [i] = Zrow[hN + i0 + i];
    }
    __syncthreads();
    float acc[TM][TN];
#pragma unroll
    for (int i = 0; i < TM; i++)
#pragma unroll
        for (int j = 0; j < TN; j++) acc[i][j] = 0.f;
    for (int j0 = 0; j0 < N_NODES; j0 += BK) {
        for (int idx = tid; idx < BM * BK; idx += 256) {
            int i  = idx / BK;
            int j  = idx % BK;
            int jj = j0 + j;
            int a  = adj[(long)(i0 + i) * N_NODES + jj];
            float e = a ? lrelu(sf1[i] + f2[hN + jj]) : NEG_INF;
            Ps[j][i] = __expf(e - sm[i]);
        }
        for (int idx = tid; idx < BK * (BN / 4); idx += 256) {
            int r = idx / (BN / 4);
            int c = idx % (BN / 4);
            float4 v = *(const float4*)&Whv[whBase + (long)(j0 + r) * BN + c * 4];
            *(float4*)&Whs[r][c * 4] = v;
        }
        __syncthreads();
#pragma unroll
        for (int kk = 0; kk < BK; kk++) {
            float a[TM], b[TN];
#pragma unroll
            for (int i = 0; i < TM; i++) a[i] = Ps[kk][ty * TM + i];
#pragma unroll
            for (int j = 0; j < TN; j++) b[j] = Whs[kk][tx * TN + j];
#pragma unroll
            for (int i = 0; i < TM; i++)
#pragma unroll
                for (int j = 0; j < TN; j++) acc[i][j] = fmaf(a[i], b[j], acc[i][j]);
        }
        __syncthreads();
    }
#pragma unroll
    for (int i = 0; i < TM; i++) {
        int r = ty * TM + i;
        float invZ = 1.f / sZ[r];
#pragma unroll
        for (int j = 0; j < TN; j++) {
            float v = acc[i][j] * invZ;
            v = v > 0.f ? v : expm1f(v);
            out[(long)(i0 + r) * outStride + colOff + tx * TN + j] = v;
        }
    }
}

// ---------------- final log_softmax ----------------
__global__ void lsm_kernel(const float* __restrict__ in, float* __restrict__ out)
{
    int warp = (blockIdx.x * blockDim.x + threadIdx.x) >> 5;
    int lane = threadIdx.x & 31;
    if (warp >= N_NODES) return;
    const float* row = in + (long)warp * NCLASS;
    float v0 = row[lane];
    float v1 = row[lane + 32];
    float m = fmaxf(v0, v1);
#pragma unroll
    for (int o = 16; o > 0; o >>= 1) m = fmaxf(m, __shfl_xor_sync(0xffffffffu, m, o));
    float s = expf(v0 - m) + expf(v1 - m);
#pragma unroll
    for (int o = 16; o > 0; o >>= 1) s += __shfl_xor_sync(0xffffffffu, s, o);
    float ls = m + logf(s);
    out[(long)warp * NCLASS + lane]      = v0 - ls;
    out[(long)warp * NCLASS + lane + 32] = v1 - ls;
}

// ---------------- launch ----------------
extern "C" void kernel_launch(void* const* d_in, const int* in_sizes, int n_in,
                              void* d_out, int out_size)
{
    const float* x   = (const float*)d_in[0];
    const int*   adj = (const int*)  d_in[1];
    const float* W   = (const float*)d_in[2];
    const float* a1  = (const float*)d_in[3];
    const float* a2  = (const float*)d_in[4];
    const float* Wo  = (const float*)d_in[5];
    const float* ao1 = (const float*)d_in[6];
    const float* ao2 = (const float*)d_in[7];
    float* out = (float*)d_out;

    float *Wh, *f1, *f2, *m, *hcat, *Who, *g1d, *g2d, *mo, *Zo, *obuf;
    uint4* bfrag;
    cudaGetSymbolAddress((void**)&Wh,    g_Wh);
    cudaGetSymbolAddress((void**)&f1,    g_f1);
    cudaGetSymbolAddress((void**)&f2,    g_f2);
    cudaGetSymbolAddress((void**)&m,     g_m);
    cudaGetSymbolAddress((void**)&hcat,  g_hcat);
    cudaGetSymbolAddress((void**)&Who,   g_Who);
    cudaGetSymbolAddress((void**)&g1d,   g_g1);
    cudaGetSymbolAddress((void**)&g2d,   g_g2);
    cudaGetSymbolAddress((void**)&mo,    g_mo);
    cudaGetSymbolAddress((void**)&Zo,    g_Zo);
    cudaGetSymbolAddress((void**)&obuf,  g_obuf);
    cudaGetSymbolAddress((void**)&bfrag, g_bfrag);

    // 1) Wh[h] = x @ W[h]
    {
        dim3 grid(1, N_NODES / 128, NHEADS);
        sgemm_kernel<128, 128, 16, 8, 8><<<grid, 256>>>(
            x, W, Wh, N_NODES, NHID, NFEAT,
            (long)NFEAT * NHID, (long)N_NODES * NHID);
    }
    // 2) f1, f2
    dots_kernel<<<(NHEADS * N_NODES) / 8, 256>>>(Wh, a1, a2, f1, f2, NHID, N_NODES, NHEADS * N_NODES);
    // 3) layer-1 m via masked-max of f2 (lrelu monotone)
    maxstat_kernel<<<N_NODES, 256>>>(adj, f1, f2, m);
    // 4) pack Wh into split-bf16 B fragments
    {
        dim3 grid(NCHUNK, NHEADS);
        prep_bfrag_kernel<<<grid, 512>>>(Wh, bfrag);
    }
    // 5) tensor-core attention apply layer 1 (+Z in-register, ELU, concat)
    {
        dim3 grid(N_NODES / 128, NHEADS);
        agg_mma_kernel<<<grid, 256>>>(adj, f1, f2, m, bfrag, hcat);
    }
    // 6) Who = hcat @ Wo
    {
        dim3 grid(1, N_NODES / 64, 1);
        sgemm_kernel<64, 64, 16, 4, 4><<<grid, 256>>>(
            hcat, Wo, Who, N_NODES, NCLASS, NHEADS * NHID, 0, 0);
    }
    // 7) g1, g2
    dots_kernel<<<N_NODES / 8, 256>>>(Who, ao1, ao2, g1d, g2d, NCLASS, N_NODES, N_NODES);
    // 8) softmax stats output layer
    stats_kernel<<<N_NODES, 256>>>(adj, g1d, g2d, mo, Zo, 1);
    // 9) attention apply output layer (+ELU)
    {
        dim3 grid(1, N_NODES / 32, 1);
        gat_agg_kernel<32, 64, 2, 4><<<grid, 256>>>(
            adj, Who, g1d, g2d, mo, Zo, obuf, NCLASS, 0);
    }
    // 10) log_softmax -> d_out
    lsm_kernel<<<N_NODES / 8, 256>>>(obuf, out);
}